// round 3
// baseline (speedup 1.0000x reference)
#include <cuda_runtime.h>
#include <cstdint>

#define F 128
#define NT 4
#define MAXN 50000

// Scratch (allocation-free rule: __device__ globals). 128B-aligned: float4
// accesses and red.global.add.v4.f32 require 16B alignment.
__device__ __align__(128) float g_agg[(size_t)NT * MAXN * F]; // [t][n][f]
__device__ __align__(128) float g_cnt[NT * MAXN];             // per-(type,node) in-degree
__device__ __align__(128) float g_wcat[(NT + 1) * F * F];     // [640][128]
__device__ __align__(128) float g_bavg[F];

// ---------------------------------------------------------------------------
// 1) Zero agg + cnt
// ---------------------------------------------------------------------------
__global__ void zero_kernel(int N) {
    size_t agg4 = (size_t)NT * N * (F / 4);
    size_t cnt4 = ((size_t)NT * N) / 4;     // NT*N divisible by 4 (NT=4)
    size_t total = agg4 + cnt4;
    float4 z = make_float4(0.f, 0.f, 0.f, 0.f);
    for (size_t i = blockIdx.x * (size_t)blockDim.x + threadIdx.x; i < total;
         i += (size_t)gridDim.x * blockDim.x) {
        if (i < agg4) reinterpret_cast<float4*>(g_agg)[i] = z;
        else          reinterpret_cast<float4*>(g_cnt)[i - agg4] = z;
    }
}

// ---------------------------------------------------------------------------
// 2) Fold weights: rows [0,128) = mean_t W_self[t]; rows [128*(1+t)) = W_neigh[t]/4
// ---------------------------------------------------------------------------
__global__ void prep_w_kernel(const float* __restrict__ Wself,
                              const float* __restrict__ Wneigh,
                              const float* __restrict__ b) {
    int idx = blockIdx.x * blockDim.x + threadIdx.x;
    if (idx < F * F) {
        float s = 0.f;
        #pragma unroll
        for (int t = 0; t < NT; t++) s += Wself[t * F * F + idx];
        g_wcat[idx] = 0.25f * s;
        #pragma unroll
        for (int t = 0; t < NT; t++)
            g_wcat[(1 + t) * F * F + idx] = 0.25f * Wneigh[t * F * F + idx];
    }
    if (idx < F) {
        float s = 0.f;
        #pragma unroll
        for (int t = 0; t < NT; t++) s += b[t * F + idx];
        g_bavg[idx] = 0.25f * s;
    }
}

// ---------------------------------------------------------------------------
// 3) Edge scatter: one warp per edge, vectorized global reduction (RED.128)
//    edge_index / edge_type are int32 (JAX without x64 downcasts int64->int32).
// ---------------------------------------------------------------------------
__global__ __launch_bounds__(256) void scatter_kernel(
        const float* __restrict__ x,
        const int* __restrict__ ei,
        const int* __restrict__ et,
        int E, int N) {
    int warp = (blockIdx.x * blockDim.x + threadIdx.x) >> 5;
    int lane = threadIdx.x & 31;
    if (warp >= E) return;
    int s = __ldg(ei + warp);        // src
    int d = __ldg(ei + E + warp);    // dst
    int t = __ldg(et + warp) & 3;    // edge type (masked: safety net)
    if ((unsigned)s >= (unsigned)N || (unsigned)d >= (unsigned)N) return;  // safety net
    const float4* xs = reinterpret_cast<const float4*>(x + (size_t)s * F);
    float4 v = __ldg(xs + lane);     // 32 lanes x float4 = 128 floats
    float* dst = g_agg + ((size_t)t * N + d) * F + lane * 4;
    asm volatile("red.global.add.v4.f32 [%0], {%1,%2,%3,%4};"
                 :: "l"(dst), "f"(v.x), "f"(v.y), "f"(v.z), "f"(v.w)
                 : "memory");
    if (lane == 0) atomicAdd(g_cnt + (size_t)t * N + d, 1.0f);
}

// ---------------------------------------------------------------------------
// 4) GEMM: out[N,128] = A_cat[N,640] @ W_cat[640,128] + b_avg
//    A_cat columns: [0,128)=x, [128*(1+t),..)=g_agg[t]/max(cnt,1) (fused scale)
//    BM=64, BN=128, BK=16, 256 threads, 8x4 register tile per thread
// ---------------------------------------------------------------------------
#define BM 64
#define BN 128
#define BK 16

__global__ __launch_bounds__(256) void gemm_kernel(const float* __restrict__ x,
                                                   float* __restrict__ out,
                                                   int N) {
    __shared__ float As[BM][BK];
    __shared__ float Bs[BK][BN];

    int tid = threadIdx.x;
    int tx = tid & 31;   // 4 consecutive output cols at tx*4
    int ty = tid >> 5;   // 8 consecutive output rows at ty*8
    int m0 = blockIdx.x * BM;

    float acc[8][4];
    #pragma unroll
    for (int m = 0; m < 8; m++)
        #pragma unroll
        for (int n = 0; n < 4; n++) acc[m][n] = 0.f;

    const int KTOT = (NT + 1) * F;  // 640

    // A-load indices (fixed per thread): one float4 of As per k-tile
    int ar = tid >> 2;              // row within tile 0..63
    int ac = (tid & 3) << 2;        // col within BK chunk
    int arow = m0 + ar;
    if (arow >= N) arow = N - 1;    // clamp (stores are guarded)

    for (int kc = 0; kc < KTOT; kc += BK) {
        int srcIdx = kc >> 7;       // 0 = x, 1..4 = agg[type srcIdx-1]
        int kin = kc & 127;

        float4 av;
        float scale;
        if (srcIdx == 0) {
            av = __ldg(reinterpret_cast<const float4*>(x + (size_t)arow * F + kin + ac));
            scale = 1.0f;
        } else {
            int t = srcIdx - 1;
            av = *reinterpret_cast<const float4*>(
                     g_agg + ((size_t)t * N + arow) * F + kin + ac);
            scale = 1.0f / fmaxf(g_cnt[(size_t)t * N + arow], 1.0f);  // fused mean
        }
        av.x *= scale; av.y *= scale; av.z *= scale; av.w *= scale;
        *reinterpret_cast<float4*>(&As[ar][ac]) = av;

        // load Bs: 16x128 -> 512 float4, two per thread
        {
            const float* Bbase = g_wcat + (size_t)kc * F;
            int r0 = tid >> 5,         j0 = (tid & 31) << 2;
            int r1 = (tid + 256) >> 5;
            *reinterpret_cast<float4*>(&Bs[r0][j0]) =
                *reinterpret_cast<const float4*>(Bbase + r0 * F + j0);
            *reinterpret_cast<float4*>(&Bs[r1][j0]) =
                *reinterpret_cast<const float4*>(Bbase + r1 * F + j0);
        }
        __syncthreads();

        #pragma unroll
        for (int kk = 0; kk < BK; kk++) {
            float a[8];
            #pragma unroll
            for (int m = 0; m < 8; m++) a[m] = As[ty * 8 + m][kk];  // warp broadcast
            float4 bv = *reinterpret_cast<float4*>(&Bs[kk][tx * 4]);
            #pragma unroll
            for (int m = 0; m < 8; m++) {
                acc[m][0] += a[m] * bv.x;
                acc[m][1] += a[m] * bv.y;
                acc[m][2] += a[m] * bv.z;
                acc[m][3] += a[m] * bv.w;
            }
        }
        __syncthreads();
    }

    float4 bb = *reinterpret_cast<float4*>(&g_bavg[tx * 4]);
    #pragma unroll
    for (int m = 0; m < 8; m++) {
        int row = m0 + ty * 8 + m;
        if (row < N) {
            float4 v;
            v.x = acc[m][0] + bb.x;
            v.y = acc[m][1] + bb.y;
            v.z = acc[m][2] + bb.z;
            v.w = acc[m][3] + bb.w;
            *reinterpret_cast<float4*>(out + (size_t)row * F + tx * 4) = v;
        }
    }
}

// ---------------------------------------------------------------------------
extern "C" void kernel_launch(void* const* d_in, const int* in_sizes, int n_in,
                              void* d_out, int out_size) {
    const float* x      = (const float*)d_in[0];   // [N,128] f32
    const int*   ei     = (const int*)d_in[1];     // [2,E] int32 (JAX x64 off)
    const int*   et     = (const int*)d_in[2];     // [E]   int32
    const float* Wself  = (const float*)d_in[3];   // [4,128,128]
    const float* Wneigh = (const float*)d_in[4];   // [4,128,128]
    const float* b      = (const float*)d_in[5];   // [4,128]
    float*       out    = (float*)d_out;           // [N,128]

    int N = in_sizes[0] / F;
    int E = in_sizes[2];
    if (N > MAXN) return;  // static scratch sized for the benchmark shape

    // 1) zero scratch
    {
        size_t total4 = (size_t)NT * N * (F / 4) + ((size_t)NT * N) / 4;
        int blocks = (int)((total4 + 255) / 256);
        if (blocks > 8192) blocks = 8192;
        zero_kernel<<<blocks, 256>>>(N);
    }
    // 2) fold weights
    prep_w_kernel<<<(F * F + 255) / 256, 256>>>(Wself, Wneigh, b);
    // 3) scatter (one warp per edge)
    {
        int warpsPerBlock = 8;
        int blocks = (E + warpsPerBlock - 1) / warpsPerBlock;
        scatter_kernel<<<blocks, warpsPerBlock * 32>>>(x, ei, et, E, N);
    }
    // 4) fused GEMM + mean-normalize + bias
    gemm_kernel<<<(N + BM - 1) / BM, 256>>>(x, out, N);
}

// round 4
// speedup vs baseline: 1.0298x; 1.0298x over previous
#include <cuda_runtime.h>
#include <cstdint>

#define F 128
#define NT 4
#define MAXN 50000

// Scratch (allocation-free rule: __device__ globals). 128B-aligned: float4
// accesses and red.global.add.v4.f32 require 16B alignment.
__device__ __align__(128) float g_agg[(size_t)NT * MAXN * F]; // [t][n][f]
__device__ __align__(128) float g_cnt[NT * MAXN];             // per-(type,node) in-degree
__device__ __align__(128) float g_wcat[(NT + 1) * F * F];     // [640][128]
__device__ __align__(128) float g_bavg[F];

// ---------------------------------------------------------------------------
// 1) Zero agg + cnt
// ---------------------------------------------------------------------------
__global__ void zero_kernel(int N) {
    size_t agg4 = (size_t)NT * N * (F / 4);
    size_t cnt4 = ((size_t)NT * N) / 4;
    size_t total = agg4 + cnt4;
    float4 z = make_float4(0.f, 0.f, 0.f, 0.f);
    for (size_t i = blockIdx.x * (size_t)blockDim.x + threadIdx.x; i < total;
         i += (size_t)gridDim.x * blockDim.x) {
        if (i < agg4) reinterpret_cast<float4*>(g_agg)[i] = z;
        else          reinterpret_cast<float4*>(g_cnt)[i - agg4] = z;
    }
}

// ---------------------------------------------------------------------------
// 2) Fold weights: rows [0,128) = mean_t W_self[t]; rows [128*(1+t)) = W_neigh[t]/4
// ---------------------------------------------------------------------------
__global__ void prep_w_kernel(const float* __restrict__ Wself,
                              const float* __restrict__ Wneigh,
                              const float* __restrict__ b) {
    int idx = blockIdx.x * blockDim.x + threadIdx.x;
    if (idx < F * F) {
        float s = 0.f;
        #pragma unroll
        for (int t = 0; t < NT; t++) s += Wself[t * F * F + idx];
        g_wcat[idx] = 0.25f * s;
        #pragma unroll
        for (int t = 0; t < NT; t++)
            g_wcat[(1 + t) * F * F + idx] = 0.25f * Wneigh[t * F * F + idx];
    }
    if (idx < F) {
        float s = 0.f;
        #pragma unroll
        for (int t = 0; t < NT; t++) s += b[t * F + idx];
        g_bavg[idx] = 0.25f * s;
    }
}

// ---------------------------------------------------------------------------
// 3) Edge scatter: one warp per edge, vectorized global reduction (RED.128)
// ---------------------------------------------------------------------------
__global__ __launch_bounds__(256) void scatter_kernel(
        const float* __restrict__ x,
        const int* __restrict__ ei,
        const int* __restrict__ et,
        int E, int N) {
    int warp = (blockIdx.x * blockDim.x + threadIdx.x) >> 5;
    int lane = threadIdx.x & 31;
    if (warp >= E) return;
    int s = __ldg(ei + warp);
    int d = __ldg(ei + E + warp);
    int t = __ldg(et + warp) & 3;
    if ((unsigned)s >= (unsigned)N || (unsigned)d >= (unsigned)N) return;
    const float4* xs = reinterpret_cast<const float4*>(x + (size_t)s * F);
    float4 v = __ldg(xs + lane);
    float* dst = g_agg + ((size_t)t * N + d) * F + lane * 4;
    asm volatile("red.global.add.v4.f32 [%0], {%1,%2,%3,%4};"
                 :: "l"(dst), "f"(v.x), "f"(v.y), "f"(v.z), "f"(v.w)
                 : "memory");
    if (lane == 0) atomicAdd(g_cnt + (size_t)t * N + d, 1.0f);
}

// ---------------------------------------------------------------------------
// 4) Tensor-core GEMM (3xTF32): out[N,128] = A_cat[N,640] @ W_cat[640,128] + b
//    A_cat cols: [0,128)=x, [128*(1+t),..)=g_agg[t]/max(cnt,1) (fused mean)
//    BM=128, BN=128, BK=16; 256 threads; warp tile 32x64 (4x2 warp grid)
//    a*b ~= ahi*bhi + ahi*blo + alo*bhi  (each term one m16n8k8 tf32 mma)
// ---------------------------------------------------------------------------
#define BM 128
#define BN 128
#define BK 16
#define ALD 132   // padded leading dim for [k][m] / [k][n] smem tiles

__device__ __forceinline__ uint32_t f2tf32(float f) {
    uint32_t u;
    asm("cvt.rna.tf32.f32 %0, %1;" : "=r"(u) : "f"(f));
    return u;
}

__device__ __forceinline__ void mma_tf32(float* c, const uint32_t* a,
                                         uint32_t b0, uint32_t b1) {
    asm volatile(
        "mma.sync.aligned.m16n8k8.row.col.f32.tf32.tf32.f32 "
        "{%0,%1,%2,%3}, {%4,%5,%6,%7}, {%8,%9}, {%0,%1,%2,%3};"
        : "+f"(c[0]), "+f"(c[1]), "+f"(c[2]), "+f"(c[3])
        : "r"(a[0]), "r"(a[1]), "r"(a[2]), "r"(a[3]), "r"(b0), "r"(b1));
}

__global__ __launch_bounds__(256, 2) void gemm_kernel(const float* __restrict__ x,
                                                      float* __restrict__ out,
                                                      int N) {
    // [k][m] layout so fragment loads are along m (padded rows kill conflicts)
    __shared__ uint32_t As_hi[BK][ALD];
    __shared__ uint32_t As_lo[BK][ALD];
    __shared__ uint32_t Bs_hi[BK][ALD];
    __shared__ uint32_t Bs_lo[BK][ALD];

    int tid  = threadIdx.x;
    int lane = tid & 31;
    int w    = tid >> 5;
    int warpM = w & 3;          // 4 warp rows of 32
    int warpN = w >> 2;         // 2 warp cols of 64
    int g = lane >> 2;          // group id 0..7
    int t = lane & 3;           // thread-in-group 0..3
    int m0 = blockIdx.x * BM;

    float acc[2][8][4];
    #pragma unroll
    for (int mi = 0; mi < 2; mi++)
        #pragma unroll
        for (int ni = 0; ni < 8; ni++)
            #pragma unroll
            for (int j = 0; j < 4; j++) acc[mi][ni][j] = 0.f;

    // A global-load coords: two float4 per thread per k-tile
    int ar  = tid >> 2;                 // 0..63 (second load: +64)
    int ac  = (tid & 3) << 2;           // k offset within tile {0,4,8,12}
    const int KTOT = (NT + 1) * F;      // 640

    for (int kc = 0; kc < KTOT; kc += BK) {
        int srcIdx = kc >> 7;           // 0 = x, 1..4 = agg[type-1]
        int kin = kc & 127;

        // ---- load A tile (fused mean-normalize + hi/lo tf32 split) ----
        #pragma unroll
        for (int l = 0; l < 2; l++) {
            int r = ar + l * 64;
            int arow = m0 + r;
            if (arow >= N) arow = N - 1;           // clamp; stores guarded
            float4 av; float scale;
            if (srcIdx == 0) {
                av = __ldg(reinterpret_cast<const float4*>(
                         x + (size_t)arow * F + kin + ac));
                scale = 1.0f;
            } else {
                int ty = srcIdx - 1;
                av = *reinterpret_cast<const float4*>(
                         g_agg + ((size_t)ty * N + arow) * F + kin + ac);
                scale = 1.0f / fmaxf(g_cnt[(size_t)ty * N + arow], 1.0f);
            }
            float vv[4] = {av.x * scale, av.y * scale, av.z * scale, av.w * scale};
            #pragma unroll
            for (int j = 0; j < 4; j++) {
                uint32_t hi = f2tf32(vv[j]);
                float lo = vv[j] - __uint_as_float(hi);
                As_hi[ac + j][r] = hi;
                As_lo[ac + j][r] = f2tf32(lo);
            }
        }

        // ---- load B tile (hi/lo tf32 split) ----
        #pragma unroll
        for (int l = 0; l < 2; l++) {
            int p = tid + l * 256;
            int br = p >> 5;                        // 0..15
            int bc = (p & 31) << 2;                 // 0..124
            float4 bv = *reinterpret_cast<const float4*>(
                            g_wcat + (size_t)(kc + br) * F + bc);
            float vv[4] = {bv.x, bv.y, bv.z, bv.w};
            #pragma unroll
            for (int j = 0; j < 4; j++) {
                uint32_t hi = f2tf32(vv[j]);
                float lo = vv[j] - __uint_as_float(hi);
                Bs_hi[br][bc + j] = hi;
                Bs_lo[br][bc + j] = f2tf32(lo);
            }
        }
        __syncthreads();

        // ---- mma over 2 k8 steps ----
        #pragma unroll
        for (int ks = 0; ks < 2; ks++) {
            int k0 = ks * 8;
            uint32_t ahi[2][4], alo[2][4];
            #pragma unroll
            for (int mi = 0; mi < 2; mi++) {
                int mrow = warpM * 32 + mi * 16 + g;
                ahi[mi][0] = As_hi[k0 + t][mrow];
                ahi[mi][1] = As_hi[k0 + t][mrow + 8];
                ahi[mi][2] = As_hi[k0 + t + 4][mrow];
                ahi[mi][3] = As_hi[k0 + t + 4][mrow + 8];
                alo[mi][0] = As_lo[k0 + t][mrow];
                alo[mi][1] = As_lo[k0 + t][mrow + 8];
                alo[mi][2] = As_lo[k0 + t + 4][mrow];
                alo[mi][3] = As_lo[k0 + t + 4][mrow + 8];
            }
            #pragma unroll
            for (int ni = 0; ni < 8; ni++) {
                int ncol = warpN * 64 + ni * 8 + g;
                uint32_t bh0 = Bs_hi[k0 + t][ncol];
                uint32_t bh1 = Bs_hi[k0 + t + 4][ncol];
                uint32_t bl0 = Bs_lo[k0 + t][ncol];
                uint32_t bl1 = Bs_lo[k0 + t + 4][ncol];
                #pragma unroll
                for (int mi = 0; mi < 2; mi++) {
                    mma_tf32(acc[mi][ni], ahi[mi], bh0, bh1);
                    mma_tf32(acc[mi][ni], ahi[mi], bl0, bl1);
                    mma_tf32(acc[mi][ni], alo[mi], bh0, bh1);
                }
            }
        }
        __syncthreads();
    }

    // ---- epilogue: bias + store ----
    #pragma unroll
    for (int ni = 0; ni < 8; ni++) {
        int c0 = warpN * 64 + ni * 8 + 2 * t;
        float b0 = g_bavg[c0];
        float b1 = g_bavg[c0 + 1];
        #pragma unroll
        for (int mi = 0; mi < 2; mi++) {
            int r0 = m0 + warpM * 32 + mi * 16 + g;
            if (r0 < N) {
                float2 v = make_float2(acc[mi][ni][0] + b0, acc[mi][ni][1] + b1);
                *reinterpret_cast<float2*>(out + (size_t)r0 * F + c0) = v;
            }
            int r1 = r0 + 8;
            if (r1 < N) {
                float2 v = make_float2(acc[mi][ni][2] + b0, acc[mi][ni][3] + b1);
                *reinterpret_cast<float2*>(out + (size_t)r1 * F + c0) = v;
            }
        }
    }
}

// ---------------------------------------------------------------------------
extern "C" void kernel_launch(void* const* d_in, const int* in_sizes, int n_in,
                              void* d_out, int out_size) {
    const float* x      = (const float*)d_in[0];   // [N,128] f32
    const int*   ei     = (const int*)d_in[1];     // [2,E] int32
    const int*   et     = (const int*)d_in[2];     // [E]   int32
    const float* Wself  = (const float*)d_in[3];   // [4,128,128]
    const float* Wneigh = (const float*)d_in[4];   // [4,128,128]
    const float* b      = (const float*)d_in[5];   // [4,128]
    float*       out    = (float*)d_out;           // [N,128]

    int N = in_sizes[0] / F;
    int E = in_sizes[2];
    if (N > MAXN) return;

    {
        size_t total4 = (size_t)NT * N * (F / 4) + ((size_t)NT * N) / 4;
        int blocks = (int)((total4 + 255) / 256);
        if (blocks > 8192) blocks = 8192;
        zero_kernel<<<blocks, 256>>>(N);
    }
    prep_w_kernel<<<(F * F + 255) / 256, 256>>>(Wself, Wneigh, b);
    {
        int warpsPerBlock = 8;
        int blocks = (E + warpsPerBlock - 1) / warpsPerBlock;
        scatter_kernel<<<blocks, warpsPerBlock * 32>>>(x, ei, et, E, N);
    }
    gemm_kernel<<<(N + BM - 1) / BM, 256>>>(x, out, N);
}

// round 6
// speedup vs baseline: 1.2223x; 1.1868x over previous
#include <cuda_runtime.h>
#include <cstdint>

#define F 128
#define NT 4
#define MAXN 50000

__device__ __align__(128) float g_agg[(size_t)NT * MAXN * F]; // [t][n][f]
__device__ __align__(128) float g_cnt[NT * MAXN];             // per-(type,node) in-degree
__device__ __align__(128) float g_wcat[(NT + 1) * F * F];     // [640][128]
__device__ __align__(128) float g_bavg[F];

// ---------------------------------------------------------------------------
// 1) Zero agg + cnt
// ---------------------------------------------------------------------------
__global__ void zero_kernel(int N) {
    size_t agg4 = (size_t)NT * N * (F / 4);
    size_t cnt4 = ((size_t)NT * N) / 4;
    size_t total = agg4 + cnt4;
    float4 z = make_float4(0.f, 0.f, 0.f, 0.f);
    for (size_t i = blockIdx.x * (size_t)blockDim.x + threadIdx.x; i < total;
         i += (size_t)gridDim.x * blockDim.x) {
        if (i < agg4) reinterpret_cast<float4*>(g_agg)[i] = z;
        else          reinterpret_cast<float4*>(g_cnt)[i - agg4] = z;
    }
}

// ---------------------------------------------------------------------------
// 2) Fold weights
// ---------------------------------------------------------------------------
__global__ void prep_w_kernel(const float* __restrict__ Wself,
                              const float* __restrict__ Wneigh,
                              const float* __restrict__ b) {
    int idx = blockIdx.x * blockDim.x + threadIdx.x;
    if (idx < F * F) {
        float s = 0.f;
        #pragma unroll
        for (int t = 0; t < NT; t++) s += Wself[t * F * F + idx];
        g_wcat[idx] = 0.25f * s;
        #pragma unroll
        for (int t = 0; t < NT; t++)
            g_wcat[(1 + t) * F * F + idx] = 0.25f * Wneigh[t * F * F + idx];
    }
    if (idx < F) {
        float s = 0.f;
        #pragma unroll
        for (int t = 0; t < NT; t++) s += b[t * F + idx];
        g_bavg[idx] = 0.25f * s;
    }
}

// ---------------------------------------------------------------------------
// 3) Edge scatter: one warp per edge, RED.128
// ---------------------------------------------------------------------------
__global__ __launch_bounds__(256) void scatter_kernel(
        const float* __restrict__ x,
        const int* __restrict__ ei,
        const int* __restrict__ et,
        int E, int N) {
    int warp = (blockIdx.x * blockDim.x + threadIdx.x) >> 5;
    int lane = threadIdx.x & 31;
    if (warp >= E) return;
    int s = __ldg(ei + warp);
    int d = __ldg(ei + E + warp);
    int t = __ldg(et + warp) & 3;
    if ((unsigned)s >= (unsigned)N || (unsigned)d >= (unsigned)N) return;
    const float4* xs = reinterpret_cast<const float4*>(x + (size_t)s * F);
    float4 v = __ldg(xs + lane);
    float* dst = g_agg + ((size_t)t * N + d) * F + lane * 4;
    asm volatile("red.global.add.v4.f32 [%0], {%1,%2,%3,%4};"
                 :: "l"(dst), "f"(v.x), "f"(v.y), "f"(v.z), "f"(v.w)
                 : "memory");
    if (lane == 0) atomicAdd(g_cnt + (size_t)t * N + d, 1.0f);
}

// ---------------------------------------------------------------------------
// 4) Tensor-core GEMM, 3-term bf16 emulation of fp32:
//    a*b ~= ahi*bhi + ahi*blo + alo*bhi   (m16n8k16 bf16 mma, fp32 accum)
//    out[N,128] = A_cat[N,640] @ W_cat[640,128] + b_avg, mean fused in A-load.
//    BM=128, BN=128, BK=16; 256 thr; warp tile 32x64; double-buffered smem,
//    register prefetch, ONE __syncthreads per k-tile.
// ---------------------------------------------------------------------------
#define BM 128
#define BN 128
#define BK 16
#define APAD 12   // u32 (bf16x2 k-pairs) per A row: 8 used, pad->12
#define BPAD 10   // u32 per B col: 8 used, pad->10

// pack two floats as bf16x2: flo -> bits[15:0], fhi -> bits[31:16]
__device__ __forceinline__ uint32_t pack_bf16x2(float flo, float fhi) {
    uint32_t r;
    asm("cvt.rn.bf16x2.f32 %0, %1, %2;" : "=r"(r) : "f"(fhi), "f"(flo));
    return r;
}
// float value of bf16(f)
__device__ __forceinline__ float bf16_round(float f) {
    uint32_t u;
    asm("cvt.rn.bf16x2.f32 %0, %1, %2;" : "=r"(u) : "f"(0.f), "f"(f));
    return __uint_as_float(u << 16);
}

__device__ __forceinline__ void mma_bf16(float* c, const uint32_t* a,
                                         uint32_t b0, uint32_t b1) {
    asm volatile(
        "mma.sync.aligned.m16n8k16.row.col.f32.bf16.bf16.f32 "
        "{%0,%1,%2,%3}, {%4,%5,%6,%7}, {%8,%9}, {%0,%1,%2,%3};"
        : "+f"(c[0]), "+f"(c[1]), "+f"(c[2]), "+f"(c[3])
        : "r"(a[0]), "r"(a[1]), "r"(a[2]), "r"(a[3]), "r"(b0), "r"(b1));
}

// ---- global->register tile prefetch -------------------------------------
__device__ __forceinline__ void loadTileG(const float* __restrict__ x, int N,
                                          int m0, int tid, int kc,
                                          float4 aReg[2], float bR0[4], float bR1[4]) {
    int srcIdx = kc >> 7;           // 0 = x, 1..4 = agg[type-1]
    int kin = kc & 127;
    #pragma unroll
    for (int l = 0; l < 2; l++) {
        int i = tid + l * 256;
        int r = i >> 2;
        int kq = (i & 3) << 2;
        int arow = m0 + r;
        if (arow >= N) arow = N - 1;
        float4 av; float sc;
        if (srcIdx == 0) {
            av = __ldg(reinterpret_cast<const float4*>(
                     x + (size_t)arow * F + kin + kq));
            sc = 1.0f;
        } else {
            int ty = srcIdx - 1;
            av = *reinterpret_cast<const float4*>(
                     g_agg + ((size_t)ty * N + arow) * F + kin + kq);
            sc = 1.0f / fmaxf(g_cnt[(size_t)ty * N + arow], 1.0f);
        }
        av.x *= sc; av.y *= sc; av.z *= sc; av.w *= sc;
        aReg[l] = av;
    }
    #pragma unroll
    for (int it = 0; it < 4; it++) {
        int idx = tid + it * 256;
        int n  = idx & 127;
        int kp = idx >> 7;
        bR0[it] = __ldg(g_wcat + (size_t)(kc + 2 * kp) * F + n);
        bR1[it] = __ldg(g_wcat + (size_t)(kc + 2 * kp + 1) * F + n);
    }
}

__global__ __launch_bounds__(256, 2) void gemm_kernel(const float* __restrict__ x,
                                                      float* __restrict__ out,
                                                      int N) {
    // A: [m][k-pair] bf16x2, hi & lo planes. B: [n][k-pair].
    __shared__ uint32_t As_h[2][BM][APAD];
    __shared__ uint32_t As_l[2][BM][APAD];
    __shared__ uint32_t Bs_h[2][BN][BPAD];
    __shared__ uint32_t Bs_l[2][BN][BPAD];

    int tid  = threadIdx.x;
    int lane = tid & 31;
    int w    = tid >> 5;
    int warpM = w & 3;           // 4 warp rows of 32
    int warpN = w >> 2;          // 2 warp cols of 64
    int g  = lane >> 2;          // 0..7
    int tq = lane & 3;           // 0..3
    int m0 = blockIdx.x * BM;

    float acc[2][8][4];
    #pragma unroll
    for (int mi = 0; mi < 2; mi++)
        #pragma unroll
        for (int ni = 0; ni < 8; ni++)
            #pragma unroll
            for (int j = 0; j < 4; j++) acc[mi][ni][j] = 0.f;

    const int KTOT = (NT + 1) * F;       // 640
    const int T = KTOT / BK;             // 40

    float4 aReg[2];
    float  bR0[4], bR1[4];

    // register -> smem (one buffer)
    #define STORE_TILE(buf)                                                    \
    do {                                                                       \
        _Pragma("unroll")                                                      \
        for (int l = 0; l < 2; l++) {                                          \
            int i = tid + l * 256;                                             \
            int r = i >> 2;                                                    \
            int kp = (i & 3) << 1;                                             \
            float v0 = aReg[l].x, v1 = aReg[l].y;                              \
            float v2 = aReg[l].z, v3 = aReg[l].w;                              \
            float h0 = bf16_round(v0), h1 = bf16_round(v1);                    \
            float h2 = bf16_round(v2), h3 = bf16_round(v3);                    \
            As_h[buf][r][kp]     = pack_bf16x2(v0, v1);                        \
            As_h[buf][r][kp + 1] = pack_bf16x2(v2, v3);                        \
            As_l[buf][r][kp]     = pack_bf16x2(v0 - h0, v1 - h1);              \
            As_l[buf][r][kp + 1] = pack_bf16x2(v2 - h2, v3 - h3);              \
        }                                                                      \
        _Pragma("unroll")                                                      \
        for (int it = 0; it < 4; it++) {                                       \
            int idx = tid + it * 256;                                          \
            int n  = idx & 127;                                                \
            int kp = idx >> 7;                                                 \
            float f0 = bR0[it], f1 = bR1[it];                                  \
            float h0 = bf16_round(f0), h1 = bf16_round(f1);                    \
            Bs_h[buf][n][kp] = pack_bf16x2(f0, f1);                            \
            Bs_l[buf][n][kp] = pack_bf16x2(f0 - h0, f1 - h1);                  \
        }                                                                      \
    } while (0)

    loadTileG(x, N, m0, tid, 0, aReg, bR0, bR1);
    STORE_TILE(0);
    __syncthreads();

    for (int t = 0; t < T; t++) {
        int buf = t & 1;
        if (t + 1 < T)
            loadTileG(x, N, m0, tid, (t + 1) * BK, aReg, bR0, bR1);

        uint32_t ah[2][4], al[2][4];
        #pragma unroll
        for (int mi = 0; mi < 2; mi++) {
            int mrow = warpM * 32 + mi * 16 + g;
            ah[mi][0] = As_h[buf][mrow][tq];
            ah[mi][1] = As_h[buf][mrow + 8][tq];
            ah[mi][2] = As_h[buf][mrow][tq + 4];
            ah[mi][3] = As_h[buf][mrow + 8][tq + 4];
            al[mi][0] = As_l[buf][mrow][tq];
            al[mi][1] = As_l[buf][mrow + 8][tq];
            al[mi][2] = As_l[buf][mrow][tq + 4];
            al[mi][3] = As_l[buf][mrow + 8][tq + 4];
        }
        #pragma unroll
        for (int ni = 0; ni < 8; ni++) {
            int ncol = warpN * 64 + ni * 8 + g;
            uint32_t bh0 = Bs_h[buf][ncol][tq];
            uint32_t bh1 = Bs_h[buf][ncol][tq + 4];
            uint32_t bl0 = Bs_l[buf][ncol][tq];
            uint32_t bl1 = Bs_l[buf][ncol][tq + 4];
            #pragma unroll
            for (int mi = 0; mi < 2; mi++) {
                mma_bf16(acc[mi][ni], ah[mi], bh0, bh1);
                mma_bf16(acc[mi][ni], ah[mi], bl0, bl1);
                mma_bf16(acc[mi][ni], al[mi], bh0, bh1);
            }
        }

        if (t + 1 < T) STORE_TILE(buf ^ 1);   // disjoint buffer
        __syncthreads();
    }

    // epilogue: bias + store
    #pragma unroll
    for (int ni = 0; ni < 8; ni++) {
        int c0 = warpN * 64 + ni * 8 + 2 * tq;
        float b0 = g_bavg[c0];
        float b1 = g_bavg[c0 + 1];
        #pragma unroll
        for (int mi = 0; mi < 2; mi++) {
            int r0 = m0 + warpM * 32 + mi * 16 + g;
            if (r0 < N) {
                float2 v = make_float2(acc[mi][ni][0] + b0, acc[mi][ni][1] + b1);
                *reinterpret_cast<float2*>(out + (size_t)r0 * F + c0) = v;
            }
            int r1 = r0 + 8;
            if (r1 < N) {
                float2 v = make_float2(acc[mi][ni][2] + b0, acc[mi][ni][3] + b1);
                *reinterpret_cast<float2*>(out + (size_t)r1 * F + c0) = v;
            }
        }
    }
    #undef STORE_TILE
}

// ---------------------------------------------------------------------------
extern "C" void kernel_launch(void* const* d_in, const int* in_sizes, int n_in,
                              void* d_out, int out_size) {
    const float* x      = (const float*)d_in[0];   // [N,128] f32
    const int*   ei     = (const int*)d_in[1];     // [2,E] int32
    const int*   et     = (const int*)d_in[2];     // [E]   int32
    const float* Wself  = (const float*)d_in[3];   // [4,128,128]
    const float* Wneigh = (const float*)d_in[4];   // [4,128,128]
    const float* b      = (const float*)d_in[5];   // [4,128]
    float*       out    = (float*)d_out;           // [N,128]

    int N = in_sizes[0] / F;
    int E = in_sizes[2];
    if (N > MAXN) return;

    {
        size_t total4 = (size_t)NT * N * (F / 4) + ((size_t)NT * N) / 4;
        int blocks = (int)((total4 + 255) / 256);
        if (blocks > 8192) blocks = 8192;
        zero_kernel<<<blocks, 256>>>(N);
    }
    prep_w_kernel<<<(F * F + 255) / 256, 256>>>(Wself, Wneigh, b);
    {
        int warpsPerBlock = 8;
        int blocks = (E + warpsPerBlock - 1) / warpsPerBlock;
        scatter_kernel<<<blocks, warpsPerBlock * 32>>>(x, ei, et, E, N);
    }
    gemm_kernel<<<(N + BM - 1) / BM, 256>>>(x, out, N);
}

// round 7
// speedup vs baseline: 2.0864x; 1.7070x over previous
#include <cuda_runtime.h>
#include <cstdint>

#define F 128
#define NT 4
#define MAXN 50000
#define MAXE 800000
#define NSEG (NT * MAXN)          // segments = (dst,type)

// ---- scratch (__device__ globals; allocation-free rule) -------------------
__device__ __align__(128) float g_mean[(size_t)NT * MAXN * F]; // normalized mean agg [t][n][f]
__device__ __align__(128) int   g_hist[NSEG + 1];
__device__ __align__(128) int   g_segstart[NSEG + 1];
__device__ __align__(128) int   g_cursor[NSEG];
__device__ __align__(128) int   g_srcs[MAXE];
__device__ __align__(128) int   g_bsum[1024];                  // block partials for scan
__device__ __align__(128) int   g_boff[1024];
__device__ __align__(128) float g_wcat[(NT + 1) * F * F];      // [640][128] folded fp32
__device__ __align__(128) uint32_t g_wb_h[(NT + 1) * F / 2 * F]; // bf16x2 hi plane [kpair][n]
__device__ __align__(128) uint32_t g_wb_l[(NT + 1) * F / 2 * F]; // bf16x2 lo plane
__device__ __align__(128) float g_bavg[F];

// ---- bf16 helpers ---------------------------------------------------------
__device__ __forceinline__ uint32_t pack_bf16x2(float flo, float fhi) {
    uint32_t r;
    asm("cvt.rn.bf16x2.f32 %0, %1, %2;" : "=r"(r) : "f"(fhi), "f"(flo));
    return r;
}
__device__ __forceinline__ float bf16_round(float f) {
    uint32_t u;
    asm("cvt.rn.bf16x2.f32 %0, %1, %2;" : "=r"(u) : "f"(0.f), "f"(f));
    return __uint_as_float(u << 16);
}
__device__ __forceinline__ void mma_bf16(float* c, const uint32_t* a,
                                         uint32_t b0, uint32_t b1) {
    asm volatile(
        "mma.sync.aligned.m16n8k16.row.col.f32.bf16.bf16.f32 "
        "{%0,%1,%2,%3}, {%4,%5,%6,%7}, {%8,%9}, {%0,%1,%2,%3};"
        : "+f"(c[0]), "+f"(c[1]), "+f"(c[2]), "+f"(c[3])
        : "r"(a[0]), "r"(a[1]), "r"(a[2]), "r"(a[3]), "r"(b0), "r"(b1));
}

// ---------------------------------------------------------------------------
// W prep: fold weights into g_wcat (fp32) + bias
// ---------------------------------------------------------------------------
__global__ void prep_w_kernel(const float* __restrict__ Wself,
                              const float* __restrict__ Wneigh,
                              const float* __restrict__ b) {
    int idx = blockIdx.x * blockDim.x + threadIdx.x;
    if (idx < F * F) {
        float s = 0.f;
        #pragma unroll
        for (int t = 0; t < NT; t++) s += Wself[t * F * F + idx];
        g_wcat[idx] = 0.25f * s;
        #pragma unroll
        for (int t = 0; t < NT; t++)
            g_wcat[(1 + t) * F * F + idx] = 0.25f * Wneigh[t * F * F + idx];
    }
    if (idx < F) {
        float s = 0.f;
        #pragma unroll
        for (int t = 0; t < NT; t++) s += b[t * F + idx];
        g_bavg[idx] = 0.25f * s;
    }
}

// g_wcat -> bf16 hi/lo planes, layout [kpair][n] (coalesced GEMM loads)
__global__ void prep_wb_kernel() {
    int idx = blockIdx.x * blockDim.x + threadIdx.x;  // over 320*128
    const int KP = (NT + 1) * F / 2;                  // 320
    if (idx >= KP * F) return;
    int kp = idx >> 7;
    int n  = idx & 127;
    float f0 = g_wcat[(2 * kp) * F + n];
    float f1 = g_wcat[(2 * kp + 1) * F + n];
    g_wb_h[idx] = pack_bf16x2(f0, f1);
    g_wb_l[idx] = pack_bf16x2(f0 - bf16_round(f0), f1 - bf16_round(f1));
}

// ---------------------------------------------------------------------------
// Aggregation: counting sort by (dst,type) + segmented gather-mean
// seg id = (d << 2) | t
// ---------------------------------------------------------------------------
__global__ void zero_hist_kernel(int S) {
    int i = blockIdx.x * blockDim.x + threadIdx.x;
    if (i <= S) g_hist[i] = 0;
}

__global__ void hist_kernel(const int* __restrict__ ei,
                            const int* __restrict__ et, int E, int N) {
    int e = blockIdx.x * blockDim.x + threadIdx.x;
    if (e >= E) return;
    int s = __ldg(ei + e);
    int d = __ldg(ei + E + e);
    int t = __ldg(et + e) & 3;
    if ((unsigned)s >= (unsigned)N || (unsigned)d >= (unsigned)N) return;
    atomicAdd(&g_hist[(d << 2) | t], 1);
}

// scan step a: per-block exclusive scan of 256 hist entries + block totals
__global__ void scan_a_kernel(int S) {
    __shared__ int sm[256];
    int lt = threadIdx.x;
    int i = blockIdx.x * 256 + lt;
    int h = (i < S) ? g_hist[i] : 0;
    sm[lt] = h;
    __syncthreads();
    #pragma unroll
    for (int d = 1; d < 256; d <<= 1) {
        int v = (lt >= d) ? sm[lt - d] : 0;
        __syncthreads();
        sm[lt] += v;
        __syncthreads();
    }
    if (i < S) g_segstart[i] = sm[lt] - h;     // exclusive within block
    if (lt == 255) g_bsum[blockIdx.x] = sm[255];
}

// scan step b: single block scans block totals (<=1024)
__global__ void scan_b_kernel(int nb) {
    __shared__ int sm[1024];
    int lt = threadIdx.x;
    int v = (lt < nb) ? g_bsum[lt] : 0;
    sm[lt] = v;
    __syncthreads();
    #pragma unroll
    for (int d = 1; d < 1024; d <<= 1) {
        int u = (lt >= d) ? sm[lt - d] : 0;
        __syncthreads();
        sm[lt] += u;
        __syncthreads();
    }
    if (lt < nb) g_boff[lt] = sm[lt] - v;      // exclusive
}

// scan step c: add block offsets, copy to cursor, set sentinel
__global__ void scan_c_kernel(int S, int E) {
    int i = blockIdx.x * 256 + threadIdx.x;
    if (i < S) {
        int v = g_segstart[i] + g_boff[blockIdx.x];
        g_segstart[i] = v;
        g_cursor[i] = v;
    }
    if (i == 0) g_segstart[S] = E;             // sentinel (valid edges <= E)
}

__global__ void reorder_kernel(const int* __restrict__ ei,
                               const int* __restrict__ et, int E, int N) {
    int e = blockIdx.x * blockDim.x + threadIdx.x;
    if (e >= E) return;
    int s = __ldg(ei + e);
    int d = __ldg(ei + E + e);
    int t = __ldg(et + e) & 3;
    if ((unsigned)s >= (unsigned)N || (unsigned)d >= (unsigned)N) return;
    int pos = atomicAdd(&g_cursor[(d << 2) | t], 1);
    g_srcs[pos] = s;
}

// one warp per segment: gather x rows, sum, write normalized mean
__global__ __launch_bounds__(256) void gather_mean_kernel(
        const float* __restrict__ x, int N) {
    int warp = (blockIdx.x * blockDim.x + threadIdx.x) >> 5;
    int lane = threadIdx.x & 31;
    int S = N << 2;
    if (warp >= S) return;
    int t = warp & 3;
    int d = warp >> 2;
    int p0 = g_segstart[warp];
    int p1 = g_segstart[warp + 1];
    float4 acc = make_float4(0.f, 0.f, 0.f, 0.f);
    for (int p = p0; p < p1; p++) {
        int src = g_srcs[p];
        float4 v = __ldg(reinterpret_cast<const float4*>(x + (size_t)src * F) + lane);
        acc.x += v.x; acc.y += v.y; acc.z += v.z; acc.w += v.w;
    }
    float inv = (p1 > p0) ? 1.0f / (float)(p1 - p0) : 0.0f;  // empty -> 0 (matches ref)
    acc.x *= inv; acc.y *= inv; acc.z *= inv; acc.w *= inv;
    reinterpret_cast<float4*>(g_mean + ((size_t)t * N + d) * F)[lane] = acc;
}

// ---------------------------------------------------------------------------
// GEMM: out[N,128] = [x | mean_0..3] (N x 640) @ W_cat (640 x 128) + b_avg
// 3-term bf16 emulation; BM=128, BN=128, BK=16; double-buffered, reg prefetch
// ---------------------------------------------------------------------------
#define BM 128
#define BN 128
#define BK 16
#define APAD 12
#define BPAD 10

__device__ __forceinline__ void loadTileG(const float* __restrict__ x, int N,
                                          int m0, int tid, int kc,
                                          float4 aReg[2],
                                          uint32_t bh[4], uint32_t bl[4]) {
    int srcIdx = kc >> 7;           // 0 = x, 1..4 = mean[type-1]
    int kin = kc & 127;
    const float* base = (srcIdx == 0)
        ? x : (g_mean + (size_t)(srcIdx - 1) * N * F);
    #pragma unroll
    for (int l = 0; l < 2; l++) {
        int i = tid + l * 256;
        int r = i >> 2;
        int kq = (i & 3) << 2;
        int arow = m0 + r;
        if (arow >= N) arow = N - 1;
        aReg[l] = __ldg(reinterpret_cast<const float4*>(
                      base + (size_t)arow * F + kin + kq));
    }
    int kc2 = kc >> 1;              // global kpair base
    #pragma unroll
    for (int it = 0; it < 4; it++) {
        int idx = tid + it * 256;
        int n  = idx & 127;
        int kp = idx >> 7;          // 0..7... (1024 slots /128 = 8? idx<1024, kp 0..7) 
        int ga = (kc2 + kp) * F + n;
        bh[it] = __ldg(g_wb_h + ga);
        bl[it] = __ldg(g_wb_l + ga);
    }
}

__global__ __launch_bounds__(256, 2) void gemm_kernel(const float* __restrict__ x,
                                                      float* __restrict__ out,
                                                      int N) {
    __shared__ uint32_t As_h[2][BM][APAD];
    __shared__ uint32_t As_l[2][BM][APAD];
    __shared__ uint32_t Bs_h[2][BN][BPAD];
    __shared__ uint32_t Bs_l[2][BN][BPAD];

    int tid  = threadIdx.x;
    int lane = tid & 31;
    int w    = tid >> 5;
    int warpM = w & 3;
    int warpN = w >> 2;
    int g  = lane >> 2;
    int tq = lane & 3;
    int m0 = blockIdx.x * BM;

    float acc[2][8][4];
    #pragma unroll
    for (int mi = 0; mi < 2; mi++)
        #pragma unroll
        for (int ni = 0; ni < 8; ni++)
            #pragma unroll
            for (int j = 0; j < 4; j++) acc[mi][ni][j] = 0.f;

    const int KTOT = (NT + 1) * F;
    const int T = KTOT / BK;        // 40

    float4 aReg[2];
    uint32_t bh[4], bl[4];

    #define STORE_TILE(buf)                                                    \
    do {                                                                       \
        _Pragma("unroll")                                                      \
        for (int l = 0; l < 2; l++) {                                          \
            int i = tid + l * 256;                                             \
            int r = i >> 2;                                                    \
            int kp = (i & 3) << 1;                                             \
            float v0 = aReg[l].x, v1 = aReg[l].y;                              \
            float v2 = aReg[l].z, v3 = aReg[l].w;                              \
            float h0 = bf16_round(v0), h1 = bf16_round(v1);                    \
            float h2 = bf16_round(v2), h3 = bf16_round(v3);                    \
            As_h[buf][r][kp]     = pack_bf16x2(v0, v1);                        \
            As_h[buf][r][kp + 1] = pack_bf16x2(v2, v3);                        \
            As_l[buf][r][kp]     = pack_bf16x2(v0 - h0, v1 - h1);              \
            As_l[buf][r][kp + 1] = pack_bf16x2(v2 - h2, v3 - h3);              \
        }                                                                      \
        _Pragma("unroll")                                                      \
        for (int it = 0; it < 4; it++) {                                       \
            int idx = tid + it * 256;                                          \
            int n  = idx & 127;                                                \
            int kp = idx >> 7;                                                 \
            Bs_h[buf][n][kp] = bh[it];                                         \
            Bs_l[buf][n][kp] = bl[it];                                         \
        }                                                                      \
    } while (0)

    loadTileG(x, N, m0, tid, 0, aReg, bh, bl);
    STORE_TILE(0);
    __syncthreads();

    for (int t = 0; t < T; t++) {
        int buf = t & 1;
        if (t + 1 < T)
            loadTileG(x, N, m0, tid, (t + 1) * BK, aReg, bh, bl);

        uint32_t ah[2][4], al[2][4];
        #pragma unroll
        for (int mi = 0; mi < 2; mi++) {
            int mrow = warpM * 32 + mi * 16 + g;
            ah[mi][0] = As_h[buf][mrow][tq];
            ah[mi][1] = As_h[buf][mrow + 8][tq];
            ah[mi][2] = As_h[buf][mrow][tq + 4];
            ah[mi][3] = As_h[buf][mrow + 8][tq + 4];
            al[mi][0] = As_l[buf][mrow][tq];
            al[mi][1] = As_l[buf][mrow + 8][tq];
            al[mi][2] = As_l[buf][mrow][tq + 4];
            al[mi][3] = As_l[buf][mrow + 8][tq + 4];
        }
        #pragma unroll
        for (int ni = 0; ni < 8; ni++) {
            int ncol = warpN * 64 + ni * 8 + g;
            uint32_t bh0 = Bs_h[buf][ncol][tq];
            uint32_t bh1 = Bs_h[buf][ncol][tq + 4];
            uint32_t bl0 = Bs_l[buf][ncol][tq];
            uint32_t bl1 = Bs_l[buf][ncol][tq + 4];
            #pragma unroll
            for (int mi = 0; mi < 2; mi++) {
                mma_bf16(acc[mi][ni], ah[mi], bh0, bh1);
                mma_bf16(acc[mi][ni], ah[mi], bl0, bl1);
                mma_bf16(acc[mi][ni], al[mi], bh0, bh1);
            }
        }

        if (t + 1 < T) STORE_TILE(buf ^ 1);
        __syncthreads();
    }

    #pragma unroll
    for (int ni = 0; ni < 8; ni++) {
        int c0 = warpN * 64 + ni * 8 + 2 * tq;
        float b0 = g_bavg[c0];
        float b1 = g_bavg[c0 + 1];
        #pragma unroll
        for (int mi = 0; mi < 2; mi++) {
            int r0 = m0 + warpM * 32 + mi * 16 + g;
            if (r0 < N) {
                float2 v = make_float2(acc[mi][ni][0] + b0, acc[mi][ni][1] + b1);
                *reinterpret_cast<float2*>(out + (size_t)r0 * F + c0) = v;
            }
            int r1 = r0 + 8;
            if (r1 < N) {
                float2 v = make_float2(acc[mi][ni][2] + b0, acc[mi][ni][3] + b1);
                *reinterpret_cast<float2*>(out + (size_t)r1 * F + c0) = v;
            }
        }
    }
    #undef STORE_TILE
}

// ---------------------------------------------------------------------------
extern "C" void kernel_launch(void* const* d_in, const int* in_sizes, int n_in,
                              void* d_out, int out_size) {
    const float* x      = (const float*)d_in[0];   // [N,128] f32
    const int*   ei     = (const int*)d_in[1];     // [2,E] int32
    const int*   et     = (const int*)d_in[2];     // [E]   int32
    const float* Wself  = (const float*)d_in[3];
    const float* Wneigh = (const float*)d_in[4];
    const float* b      = (const float*)d_in[5];
    float*       out    = (float*)d_out;

    int N = in_sizes[0] / F;
    int E = in_sizes[2];
    if (N > MAXN || E > MAXE) return;

    int S = N << 2;                               // segments
    int scanBlocks = (S + 255) / 256;             // <= 1024 required by scan_b
    if (scanBlocks > 1024) return;

    // weights
    prep_w_kernel<<<(F * F + 255) / 256, 256>>>(Wself, Wneigh, b);
    prep_wb_kernel<<<((NT + 1) * F / 2 * F + 255) / 256, 256>>>();

    // counting sort by (dst,type)
    zero_hist_kernel<<<(S + 256) / 256, 256>>>(S);
    hist_kernel<<<(E + 255) / 256, 256>>>(ei, et, E, N);
    scan_a_kernel<<<scanBlocks, 256>>>(S);
    scan_b_kernel<<<1, 1024>>>(scanBlocks);
    scan_c_kernel<<<scanBlocks, 256>>>(S, E);
    reorder_kernel<<<(E + 255) / 256, 256>>>(ei, et, E, N);

    // segmented gather + mean (writes every row, incl. zeros)
    gather_mean_kernel<<<(S * 32 + 255) / 256, 256>>>(x, N);

    // fused GEMM + bias
    gemm_kernel<<<(N + BM - 1) / BM, 256>>>(x, out, N);
}